// round 1
// baseline (speedup 1.0000x reference)
#include <cuda_runtime.h>
#include <cstdint>

#define USER_NUM 200000
#define ITEM_NUM 100000
#define N_NODES  (USER_NUM + ITEM_NUM)   // 300000
#define EMB      64
#define N_EDGES  4800000

// ---------------- static device scratch (no allocation allowed) ----------------
__device__ int   g_deg[N_NODES + 1];        // degree histogram (+1 trailing zero for scan)
__device__ int   g_row_ptr[N_NODES + 1];    // CSR row pointers
__device__ int   g_cursor[N_NODES];         // scatter cursors (init = row_ptr)
__device__ int2  g_edges[N_EDGES];          // sorted (dst, val-bits) pairs
__device__ float g_bufA[(size_t)N_NODES * EMB];
__device__ float g_bufB[(size_t)N_NODES * EMB];

// ---------------- build kernels ----------------
__global__ void zero_deg_kernel() {
    int n = N_NODES + 1;
    for (int i = blockIdx.x * blockDim.x + threadIdx.x; i < n; i += gridDim.x * blockDim.x)
        g_deg[i] = 0;
}

__global__ void hist_kernel(const int* __restrict__ src) {
    for (int e = blockIdx.x * blockDim.x + threadIdx.x; e < N_EDGES; e += gridDim.x * blockDim.x)
        atomicAdd(&g_deg[src[e]], 1);
}

// single-block chunked exclusive scan over g_deg -> g_row_ptr (and g_cursor copy)
__global__ void scan_kernel() {
    const int n = N_NODES + 1;
    __shared__ int warp_sums[32];
    __shared__ int s_carry;
    if (threadIdx.x == 0) s_carry = 0;
    __syncthreads();

    const int PER_THREAD = 16;
    const int TILE = 1024 * PER_THREAD;   // 16384
    for (int base = 0; base < n; base += TILE) {
        int idx0 = base + threadIdx.x * PER_THREAD;
        int vals[PER_THREAD];
        int local = 0;
#pragma unroll
        for (int i = 0; i < PER_THREAD; i++) {
            int v = (idx0 + i < n) ? g_deg[idx0 + i] : 0;
            vals[i] = local;       // exclusive within thread
            local += v;
        }
        int lane = threadIdx.x & 31;
        int wid  = threadIdx.x >> 5;
        int incl = local;
#pragma unroll
        for (int off = 1; off < 32; off <<= 1) {
            int y = __shfl_up_sync(0xffffffffu, incl, off);
            if (lane >= off) incl += y;
        }
        if (lane == 31) warp_sums[wid] = incl;
        __syncthreads();
        if (wid == 0) {
            int w = warp_sums[lane];
#pragma unroll
            for (int off = 1; off < 32; off <<= 1) {
                int y = __shfl_up_sync(0xffffffffu, w, off);
                if (lane >= off) w += y;
            }
            warp_sums[lane] = w;   // inclusive scan of warp totals
        }
        __syncthreads();
        int excl = incl - local + (wid > 0 ? warp_sums[wid - 1] : 0) + s_carry;
#pragma unroll
        for (int i = 0; i < PER_THREAD; i++) {
            int idx = idx0 + i;
            if (idx < n) {
                int r = excl + vals[i];
                g_row_ptr[idx] = r;
                if (idx < N_NODES) g_cursor[idx] = r;
            }
        }
        __syncthreads();
        if (threadIdx.x == 0) s_carry += warp_sums[31];
        __syncthreads();
    }
}

__global__ void scatter_kernel(const int* __restrict__ src,
                               const int* __restrict__ dst,
                               const float* __restrict__ val) {
    for (int e = blockIdx.x * blockDim.x + threadIdx.x; e < N_EDGES; e += gridDim.x * blockDim.x) {
        int s = src[e];
        int p = atomicAdd(&g_cursor[s], 1);
        g_edges[p] = make_int2(dst[e], __float_as_int(val[e]));
    }
}

// concat user/item embeddings into g_bufA (float4 vectorized)
__global__ void concat_kernel(const float4* __restrict__ u, const float4* __restrict__ it) {
    const int nU = USER_NUM * EMB / 4;           // 3,200,000
    const int nT = (USER_NUM + ITEM_NUM) * EMB / 4;
    float4* out = reinterpret_cast<float4*>(g_bufA);
    for (int i = blockIdx.x * blockDim.x + threadIdx.x; i < nT; i += gridDim.x * blockDim.x)
        out[i] = (i < nU) ? u[i] : it[i - nU];
}

// ---------------- SpMM: one warp per output row, CSR gather, no atomics ----------------
// ab==0: x = g_bufA, y = g_bufB ; ab==1: x = g_bufB, y = g_bufA
__global__ void __launch_bounds__(256) spmm_kernel(float* __restrict__ acc,
                                                   int ab, int first, int write_y) {
    int gw = (blockIdx.x * blockDim.x + threadIdx.x) >> 5;
    if (gw >= N_NODES) return;
    int lane = threadIdx.x & 31;

    const float* __restrict__ x = ab ? g_bufB : g_bufA;
    float* __restrict__       y = ab ? g_bufA : g_bufB;

    int beg = g_row_ptr[gw];
    int end = g_row_ptr[gw + 1];

    float sx = 0.f, sy = 0.f;
    for (int j0 = beg; j0 < end; j0 += 32) {
        int jj = j0 + lane;
        int2 e = (jj < end) ? g_edges[jj] : make_int2(0, 0);
        int cnt = min(32, end - j0);
        for (int t = 0; t < cnt; t++) {
            int   dd = __shfl_sync(0xffffffffu, e.x, t);
            float vv = __int_as_float(__shfl_sync(0xffffffffu, e.y, t));
            float2 xv = *reinterpret_cast<const float2*>(x + ((size_t)dd << 6) + (lane << 1));
            sx = fmaf(vv, xv.x, sx);
            sy = fmaf(vv, xv.y, sy);
        }
    }

    size_t off = ((size_t)gw << 6) + (lane << 1);
    if (write_y)
        *reinterpret_cast<float2*>(y + off) = make_float2(sx, sy);

    const float inv3 = 1.0f / 3.0f;
    float2 a;
    if (first) {
        a = make_float2(sx * inv3, sy * inv3);
    } else {
        a = *reinterpret_cast<const float2*>(acc + off);
        a.x = fmaf(sx, inv3, a.x);
        a.y = fmaf(sy, inv3, a.y);
    }
    *reinterpret_cast<float2*>(acc + off) = a;
}

// ---------------- launch ----------------
extern "C" void kernel_launch(void* const* d_in, const int* in_sizes, int n_in,
                              void* d_out, int out_size) {
    const float* user_emb = (const float*)d_in[0];
    const float* item_emb = (const float*)d_in[1];
    const float* edge_val = (const float*)d_in[2];
    const int*   edge_src = (const int*)d_in[3];
    const int*   edge_dst = (const int*)d_in[4];
    float* out = (float*)d_out;

    const int TB = 256;
    const int edge_grid = (N_EDGES + TB - 1) / TB;       // 18750
    const int node_grid = (N_NODES + 1 + TB - 1) / TB;
    const int spmm_grid = (N_NODES * 32 + TB - 1) / TB;  // 37500 (8 warps/block)
    const int cat_grid  = ((USER_NUM + ITEM_NUM) * EMB / 4 + TB - 1) / TB;

    zero_deg_kernel<<<node_grid, TB>>>();
    hist_kernel<<<edge_grid, TB>>>(edge_src);
    scan_kernel<<<1, 1024>>>();
    scatter_kernel<<<edge_grid, TB>>>(edge_src, edge_dst, edge_val);
    concat_kernel<<<cat_grid, TB>>>((const float4*)user_emb, (const float4*)item_emb);

    // layer 1: x=A -> y=B, acc = y/3 (init)
    spmm_kernel<<<spmm_grid, TB>>>(out, /*ab=*/0, /*first=*/1, /*write_y=*/1);
    // layer 2: x=B -> y=A, acc += y/3
    spmm_kernel<<<spmm_grid, TB>>>(out, /*ab=*/1, /*first=*/0, /*write_y=*/1);
    // layer 3: x=A -> y=B (y not needed), acc += y/3
    spmm_kernel<<<spmm_grid, TB>>>(out, /*ab=*/0, /*first=*/0, /*write_y=*/0);
}

// round 2
// speedup vs baseline: 1.0529x; 1.0529x over previous
#include <cuda_runtime.h>
#include <cstdint>

#define USER_NUM 200000
#define ITEM_NUM 100000
#define N_NODES  (USER_NUM + ITEM_NUM)   // 300000
#define EMB      64
#define N_EDGES  4800000

// ---------------- static device scratch (no allocation allowed) ----------------
__device__ int   g_deg[N_NODES + 1];
__device__ int   g_row_ptr[N_NODES + 1];
__device__ int   g_cursor[N_NODES];
__device__ int2  g_edges[N_EDGES];          // sorted-by-src (dst, val-bits) pairs
__device__ float g_bufA[(size_t)N_NODES * EMB];   // layer-2 output
__device__ float g_bufB[(size_t)N_NODES * EMB];   // layer-1 output

// ---------------- build kernels ----------------
__global__ void zero_deg_kernel() {
    int n = N_NODES + 1;
    for (int i = blockIdx.x * blockDim.x + threadIdx.x; i < n; i += gridDim.x * blockDim.x)
        g_deg[i] = 0;
}

__global__ void hist_kernel(const int* __restrict__ src) {
    for (int e = blockIdx.x * blockDim.x + threadIdx.x; e < N_EDGES; e += gridDim.x * blockDim.x)
        atomicAdd(&g_deg[src[e]], 1);
}

// single-block chunked exclusive scan over g_deg -> g_row_ptr (+ g_cursor copy)
__global__ void scan_kernel() {
    const int n = N_NODES + 1;
    __shared__ int warp_sums[32];
    __shared__ int s_carry;
    if (threadIdx.x == 0) s_carry = 0;
    __syncthreads();

    const int PER_THREAD = 16;
    const int TILE = 1024 * PER_THREAD;
    for (int base = 0; base < n; base += TILE) {
        int idx0 = base + threadIdx.x * PER_THREAD;
        int vals[PER_THREAD];
        int local = 0;
#pragma unroll
        for (int i = 0; i < PER_THREAD; i++) {
            int v = (idx0 + i < n) ? g_deg[idx0 + i] : 0;
            vals[i] = local;
            local += v;
        }
        int lane = threadIdx.x & 31;
        int wid  = threadIdx.x >> 5;
        int incl = local;
#pragma unroll
        for (int off = 1; off < 32; off <<= 1) {
            int y = __shfl_up_sync(0xffffffffu, incl, off);
            if (lane >= off) incl += y;
        }
        if (lane == 31) warp_sums[wid] = incl;
        __syncthreads();
        if (wid == 0) {
            int w = warp_sums[lane];
#pragma unroll
            for (int off = 1; off < 32; off <<= 1) {
                int y = __shfl_up_sync(0xffffffffu, w, off);
                if (lane >= off) w += y;
            }
            warp_sums[lane] = w;
        }
        __syncthreads();
        int excl = incl - local + (wid > 0 ? warp_sums[wid - 1] : 0) + s_carry;
#pragma unroll
        for (int i = 0; i < PER_THREAD; i++) {
            int idx = idx0 + i;
            if (idx < n) {
                int r = excl + vals[i];
                g_row_ptr[idx] = r;
                if (idx < N_NODES) g_cursor[idx] = r;
            }
        }
        __syncthreads();
        if (threadIdx.x == 0) s_carry += warp_sums[31];
        __syncthreads();
    }
}

__global__ void scatter_kernel(const int* __restrict__ src,
                               const int* __restrict__ dst,
                               const float* __restrict__ val) {
    for (int e = blockIdx.x * blockDim.x + threadIdx.x; e < N_EDGES; e += gridDim.x * blockDim.x) {
        int s = src[e];
        int p = atomicAdd(&g_cursor[s], 1);
        g_edges[p] = make_int2(dst[e], __float_as_int(val[e]));
    }
}

// ---------------- SpMM: one warp per row, uniform edge loads, no shuffles ----------------
// mode 0: x = split(user,item)   -> write bufB
// mode 1: x = bufB               -> write bufA
// mode 2: x = bufA               -> out = (bufB + bufA + s)/3
__global__ void __launch_bounds__(256) spmm_kernel(const float* __restrict__ user,
                                                   const float* __restrict__ item,
                                                   float* __restrict__ out,
                                                   int mode) {
    int gw = (blockIdx.x * blockDim.x + threadIdx.x) >> 5;
    if (gw >= N_NODES) return;
    int lane = threadIdx.x & 31;
    int col  = lane << 1;   // each lane owns 2 floats

    int beg = __ldg(&g_row_ptr[gw]);
    int end = __ldg(&g_row_ptr[gw + 1]);

    float sx = 0.f, sy = 0.f;

    if (mode == 0) {
#pragma unroll 4
        for (int j = beg; j < end; j++) {
            int2 e = __ldg(&g_edges[j]);            // uniform across warp
            float vv = __int_as_float(e.y);
            const float* xr = (e.x < USER_NUM)
                ? (user + ((size_t)e.x << 6))
                : (item + ((size_t)(e.x - USER_NUM) << 6));
            float2 xv = *reinterpret_cast<const float2*>(xr + col);
            sx = fmaf(vv, xv.x, sx);
            sy = fmaf(vv, xv.y, sy);
        }
    } else {
        const float* __restrict__ x = (mode == 1) ? g_bufB : g_bufA;
#pragma unroll 4
        for (int j = beg; j < end; j++) {
            int2 e = __ldg(&g_edges[j]);            // uniform across warp
            float vv = __int_as_float(e.y);
            float2 xv = *reinterpret_cast<const float2*>(x + ((size_t)e.x << 6) + col);
            sx = fmaf(vv, xv.x, sx);
            sy = fmaf(vv, xv.y, sy);
        }
    }

    size_t off = ((size_t)gw << 6) + col;
    if (mode == 0) {
        *reinterpret_cast<float2*>(g_bufB + off) = make_float2(sx, sy);
    } else if (mode == 1) {
        *reinterpret_cast<float2*>(g_bufA + off) = make_float2(sx, sy);
    } else {
        const float inv3 = 1.0f / 3.0f;
        float2 b1 = *reinterpret_cast<const float2*>(g_bufB + off);  // layer-1 out
        float2 b2 = *reinterpret_cast<const float2*>(g_bufA + off);  // layer-2 out
        float2 r;
        r.x = (b1.x + b2.x + sx) * inv3;
        r.y = (b1.y + b2.y + sy) * inv3;
        *reinterpret_cast<float2*>(out + off) = r;
    }
}

// ---------------- launch ----------------
extern "C" void kernel_launch(void* const* d_in, const int* in_sizes, int n_in,
                              void* d_out, int out_size) {
    const float* user_emb = (const float*)d_in[0];
    const float* item_emb = (const float*)d_in[1];
    const float* edge_val = (const float*)d_in[2];
    const int*   edge_src = (const int*)d_in[3];
    const int*   edge_dst = (const int*)d_in[4];
    float* out = (float*)d_out;

    const int TB = 256;
    const int edge_grid = (N_EDGES + TB - 1) / TB;
    const int node_grid = (N_NODES + 1 + TB - 1) / TB;
    const int spmm_grid = (N_NODES * 32 + TB - 1) / TB;   // 8 warps/block

    zero_deg_kernel<<<node_grid, TB>>>();
    hist_kernel<<<edge_grid, TB>>>(edge_src);
    scan_kernel<<<1, 1024>>>();
    scatter_kernel<<<edge_grid, TB>>>(edge_src, edge_dst, edge_val);

    spmm_kernel<<<spmm_grid, TB>>>(user_emb, item_emb, out, 0);  // L1 -> bufB
    spmm_kernel<<<spmm_grid, TB>>>(user_emb, item_emb, out, 1);  // L2 -> bufA
    spmm_kernel<<<spmm_grid, TB>>>(user_emb, item_emb, out, 2);  // L3 -> out
}